// round 4
// baseline (speedup 1.0000x reference)
#include <cuda_runtime.h>
#include <cuda_bf16.h>

#define T_DIM 1024
#define F_DIM 128
#define UNROLL 8
#define N_TILES (T_DIM / UNROLL)   // 128
#define EPS_F 1e-5f

// One block per (b, c) row. 128 threads, thread = f index (coalesced).
// 3-stage software pipeline: loads run 2 tiles (16 t-steps) ahead of compute,
// so every warp keeps 8-16 loads in flight through compute AND store phases.
__global__ __launch_bounds__(128, 7)
void cumulative_groupnorm_kernel(const float* __restrict__ x,
                                 const float* __restrict__ weight,
                                 const float* __restrict__ bias,
                                 float* __restrict__ out,
                                 int C)
{
    __shared__ float s_inv[T_DIM];   // 1/(t+1) LUT (broadcast reads)
    const int f  = threadIdx.x;
    const int bc = blockIdx.x;

    #pragma unroll
    for (int i = 0; i < T_DIM / F_DIM; i++) {
        int idx = f + i * F_DIM;
        s_inv[idx] = 1.0f / (float)(idx + 1);
    }
    __syncthreads();

    const int c = bc % C;
    const float w  = weight[c];
    const float bb = bias[c];

    const size_t base = (size_t)bc * T_DIM * F_DIM + f;
    const float* __restrict__ xp = x + base;
    float* __restrict__ op = out + base;

    float sum = 0.0f, sumsq = 0.0f;

    float b0[UNROLL], b1[UNROLL], b2[UNROLL];

#define LOAD_TILE(buf, tile)                                            \
    _Pragma("unroll")                                                   \
    for (int j = 0; j < UNROLL; j++)                                    \
        buf[j] = __ldcs(xp + (size_t)((tile) * UNROLL + j) * F_DIM);

#define PROC_TILE(buf, tile)                                            \
    _Pragma("unroll")                                                   \
    for (int j = 0; j < UNROLL; j++) {                                  \
        const int  tt  = (tile) * UNROLL + j;                           \
        const float val = buf[j];                                       \
        sum   += val;                                                   \
        sumsq  = fmaf(val, val, sumsq);                                 \
        const float inv  = s_inv[tt];                                   \
        const float mean = sum * inv;                                   \
        const float var  = fmaf(-mean, mean, sumsq * inv);              \
        const float r    = rsqrtf(var + EPS_F);                         \
        __stcs(op + (size_t)tt * F_DIM, fmaf((val - mean) * r, w, bb)); \
    }

    // Prologue: tiles 0 and 1 in flight.
    LOAD_TILE(b0, 0)
    LOAD_TILE(b1, 1)

    // Main: 42 iterations x 3 tiles = tiles 0..125 computed,
    // prefetching up to tile 127. No bounds checks needed (128 tiles total).
    #pragma unroll 1
    for (int i = 0; i < N_TILES - 2; i += 3) {
        LOAD_TILE(b2, i + 2)
        PROC_TILE(b0, i)
        LOAD_TILE(b0, i + 3)
        PROC_TILE(b1, i + 1)
        LOAD_TILE(b1, i + 4)
        PROC_TILE(b2, i + 2)
    }

    // Epilogue: tiles 126, 127 (already loaded into b0, b1).
    PROC_TILE(b0, N_TILES - 2)
    PROC_TILE(b1, N_TILES - 1)

#undef LOAD_TILE
#undef PROC_TILE
}

extern "C" void kernel_launch(void* const* d_in, const int* in_sizes, int n_in,
                              void* d_out, int out_size)
{
    const float* x      = (const float*)d_in[0];
    const float* weight = (const float*)d_in[1];
    const float* bias   = (const float*)d_in[2];
    float* out          = (float*)d_out;

    const int C    = in_sizes[1];                       // 256
    const int n_bc = in_sizes[0] / (T_DIM * F_DIM);     // B*C = 1024

    cumulative_groupnorm_kernel<<<n_bc, F_DIM>>>(x, weight, bias, out, C);
}

// round 5
// speedup vs baseline: 1.0293x; 1.0293x over previous
#include <cuda_runtime.h>
#include <cuda_bf16.h>

#define T_DIM 1024
#define F_DIM 128
#define HALF_F 64
#define UNROLL 8
#define N_TILES (T_DIM / UNROLL)   // 128
#define EPS_F 1e-5f

// One block per HALF (b, c) row: 64 threads, thread = f within half.
// 2048 blocks -> ~14 CTAs/SM -> per-SM work skew ~3.6% (vs 14% at 1024 blocks).
// Distance-2 register pipeline keeps 8-16 loads in flight per warp.
// __ldcg: L2-only reads (zero reuse, skip L1 allocate).
__global__ __launch_bounds__(HALF_F, 14)
void cumulative_groupnorm_kernel(const float* __restrict__ x,
                                 const float* __restrict__ weight,
                                 const float* __restrict__ bias,
                                 float* __restrict__ out,
                                 int C)
{
    __shared__ float s_inv[T_DIM];   // 1/(t+1) LUT (broadcast reads)
    const int tid  = threadIdx.x;          // 0..63
    const int bid  = blockIdx.x;
    const int bc   = bid >> 1;              // (b, c) row
    const int fh   = (bid & 1) * HALF_F;    // which half of F

    #pragma unroll
    for (int i = 0; i < T_DIM / HALF_F; i++) {
        int idx = tid + i * HALF_F;
        s_inv[idx] = 1.0f / (float)(idx + 1);
    }
    __syncthreads();

    const int c = bc % C;
    const float w  = weight[c];
    const float bb = bias[c];

    const size_t base = (size_t)bc * T_DIM * F_DIM + fh + tid;
    const float* __restrict__ xp = x + base;
    float* __restrict__ op = out + base;

    float sum = 0.0f, sumsq = 0.0f;
    float b0[UNROLL], b1[UNROLL], b2[UNROLL];

#define LOAD_TILE(buf, tile)                                            \
    _Pragma("unroll")                                                   \
    for (int j = 0; j < UNROLL; j++)                                    \
        buf[j] = __ldcg(xp + (size_t)((tile) * UNROLL + j) * F_DIM);

#define PROC_TILE(buf, tile)                                            \
    _Pragma("unroll")                                                   \
    for (int j = 0; j < UNROLL; j++) {                                  \
        const int  tt  = (tile) * UNROLL + j;                           \
        const float val = buf[j];                                       \
        sum   += val;                                                   \
        sumsq  = fmaf(val, val, sumsq);                                 \
        const float inv  = s_inv[tt];                                   \
        const float mean = sum * inv;                                   \
        const float var  = fmaf(-mean, mean, sumsq * inv);              \
        const float r    = rsqrtf(var + EPS_F);                         \
        __stcs(op + (size_t)tt * F_DIM, fmaf((val - mean) * r, w, bb)); \
    }

    // Prologue: tiles 0 and 1 in flight (distance 2).
    LOAD_TILE(b0, 0)
    LOAD_TILE(b1, 1)

    // 42 iterations x 3 tiles: compute tiles 0..125, prefetch through 127.
    #pragma unroll 1
    for (int i = 0; i < N_TILES - 2; i += 3) {
        LOAD_TILE(b2, i + 2)
        PROC_TILE(b0, i)
        LOAD_TILE(b0, i + 3)
        PROC_TILE(b1, i + 1)
        LOAD_TILE(b1, i + 4)
        PROC_TILE(b2, i + 2)
    }

    // Epilogue: tiles 126, 127 already resident in b0, b1.
    PROC_TILE(b0, N_TILES - 2)
    PROC_TILE(b1, N_TILES - 1)

#undef LOAD_TILE
#undef PROC_TILE
}

extern "C" void kernel_launch(void* const* d_in, const int* in_sizes, int n_in,
                              void* d_out, int out_size)
{
    const float* x      = (const float*)d_in[0];
    const float* weight = (const float*)d_in[1];
    const float* bias   = (const float*)d_in[2];
    float* out          = (float*)d_out;

    const int C    = in_sizes[1];                       // 256
    const int n_bc = in_sizes[0] / (T_DIM * F_DIM);     // B*C = 1024

    cumulative_groupnorm_kernel<<<n_bc * 2, HALF_F>>>(x, weight, bias, out, C);
}